// round 10
// baseline (speedup 1.0000x reference)
#include <cuda_runtime.h>
#include <cuda_bf16.h>

// x: (256,64,25,3) f32; W_conv: (3,192) f32; W_a: (128,1) f32; out: (256,3,25,25) f32
// Verified math (R1/R3/R7):
//   xbar[j] = sum_t x[n,t,j], j=v*3+i (1/64 folded into u)
//   u{1,2}[i,k] = (1/64) sum_c W_conv[i,c*3+k]*W_a[{0,64}+c]
//   s{1,2}[v,k] = sum_i xbar[v*3+i]*u{1,2}[i,k]
//   row(0..74), col q: e = s1[(row%3)*25+q] + s2[(row/3)*3 + ((row%3)+q)%3]
//   exp(leaky(e)) = max(E1[r]*E2[c], F1[r]*F2[c]), E=exp2(L2E*s), F=exp2(0.2*L2E*s)
// R10: single-wave. grid=128, 2 samples/block, "two R9 blocks side by side":
//   600 loader threads (300/sample), 144 dedicated u lanes, 6 phase-2 warps,
//   600 phase-3 threads. All cross-sample work in PARALLEL warps.

#define TPB 800

__device__ __forceinline__ unsigned long long add2(unsigned long long a, unsigned long long b) {
    unsigned long long r;
    asm("add.rn.f32x2 %0, %1, %2;" : "=l"(r) : "l"(a), "l"(b));
    return r;
}
__device__ __forceinline__ unsigned long long mul2(unsigned long long a, unsigned long long b) {
    unsigned long long r;
    asm("mul.rn.f32x2 %0, %1, %2;" : "=l"(r) : "l"(a), "l"(b));
    return r;
}
__device__ __forceinline__ unsigned long long pack2(float lo, float hi) {
    unsigned long long r;
    asm("mov.b64 %0, {%1, %2};" : "=l"(r) : "f"(lo), "f"(hi));
    return r;
}
__device__ __forceinline__ void unpack2(unsigned long long v, float &lo, float &hi) {
    asm("mov.b64 {%0, %1}, %2;" : "=f"(lo), "=f"(hi) : "l"(v));
}
__device__ __forceinline__ float ex2a(float x) {
    float r; asm("ex2.approx.f32 %0, %1;" : "=f"(r) : "f"(x)); return r;
}

__global__ __launch_bounds__(TPB, 1)
void gat_adj_kernel(const float* __restrict__ x,
                    const float* __restrict__ Wc,
                    const float* __restrict__ Wa,
                    float* __restrict__ out)
{
    __shared__ __align__(16) float buf[2][1200];        // 16 slots x 75 cols, per sample
    __shared__ float uu[18];
    __shared__ unsigned long long ep1[2][75], ep2[2][75];

    const int n0  = blockIdx.x * 2;
    const int tid = threadIdx.x;

    if (tid < 600) {
        // ---- Loaders: 300 threads per sample, 4 LDG.128 each at t=0 ----
        const int samp = (tid >= 300);
        const int lt   = tid - 300 * samp;
        const ulonglong2* xg =
            reinterpret_cast<const ulonglong2*>(x) + (size_t)(n0 + samp) * 1200;
        ulonglong2 xa = xg[lt];
        ulonglong2 xb = xg[lt + 300];
        ulonglong2 xc = xg[lt + 600];
        ulonglong2 xd = xg[lt + 900];
        ulonglong2 s;
        s.x = add2(add2(xa.x, xb.x), add2(xc.x, xd.x));
        s.y = add2(add2(xa.y, xb.y), add2(xc.y, xd.y));
        reinterpret_cast<ulonglong2*>(buf[samp])[lt] = s; // col=(4lt+m)%75, slot=(4lt+m)/75
    } else if (tid >= 640 && tid < 784) {
        // ---- u warps: 18 outputs x 8 lanes x 8 terms, shared by both samples ----
        const int idx = tid - 640;                      // 0..143
        const int o = idx >> 3;                         // 0..17
        const int p = idx & 7;
        const int which = o / 9;
        const int rem   = o % 9;
        const int i     = rem / 3;
        const int k     = rem % 3;
        const int c0    = p * 8;
        const float* wcb = Wc + i * 192 + k;
        const float4 wa0 = *reinterpret_cast<const float4*>(Wa + which * 64 + c0);
        const float4 wa1 = *reinterpret_cast<const float4*>(Wa + which * 64 + c0 + 4);
        float acc = wcb[(c0 + 0) * 3] * wa0.x + wcb[(c0 + 1) * 3] * wa0.y
                  + wcb[(c0 + 2) * 3] * wa0.z + wcb[(c0 + 3) * 3] * wa0.w
                  + wcb[(c0 + 4) * 3] * wa1.x + wcb[(c0 + 5) * 3] * wa1.y
                  + wcb[(c0 + 6) * 3] * wa1.z + wcb[(c0 + 7) * 3] * wa1.w;
        // warps 20..23 fully in u-range; warp 24 uses lanes 0..15 only
        const unsigned mask = (tid < 768) ? 0xFFFFFFFFu : 0x0000FFFFu;
        acc += __shfl_xor_sync(mask, acc, 1);
        acc += __shfl_xor_sync(mask, acc, 2);
        acc += __shfl_xor_sync(mask, acc, 4);
        if (p == 0) uu[o] = acc * (1.0f / 64.0f);
    }
    __syncthreads();   // bar 0

    // ---- Phase 2: 6 warps (3 per sample), col = wl*27+lane ----
    if (tid < 192) {
        const int w    = tid >> 5;
        const int samp = (w >= 3);
        const int wl   = w - 3 * samp;
        const int lane = tid & 31;
        const int col  = wl * 27 + lane;
        const bool on  = (lane < 27) && (col < 75);
        const int colc = on ? col : 74;

        float xv = 0.f;
        #pragma unroll
        for (int i = 0; i < 16; i++) xv += buf[samp][i * 75 + colc];

        const int k    = lane % 3;                     // == col%3 when on (27 ≡ 0 mod 3)
        const int base = lane - k;
        const float a0 = __shfl_sync(0xffffffffu, xv, base);
        const float a1 = __shfl_sync(0xffffffffu, xv, base + 1);
        const float a2 = __shfl_sync(0xffffffffu, xv, base + 2);

        const float s1 = a0 * uu[k]     + a1 * uu[3 + k]  + a2 * uu[6 + k];
        const float s2 = a0 * uu[9 + k] + a1 * uu[12 + k] + a2 * uu[15 + k];
        const float L2E  = 1.4426950408889634f;
        const float L2E5 = 0.2f * L2E;
        const float E1 = ex2a(s1 * L2E),  F1 = ex2a(s1 * L2E5);
        const float E2 = ex2a(s2 * L2E),  F2 = ex2a(s2 * L2E5);
        if (on) {
            ep1[samp][col] = pack2(E1, F1);
            ep2[samp][col] = pack2(E2, F2);
        }
    }
    __syncthreads();   // bar 1

    // ---- Phase 3: softmax, 4 threads/row, 150 rows (both samples) ----
    {
        int row2 = tid >> 2;
        const bool act = (row2 < 150);
        if (row2 > 149) row2 = 149;             // tid 600..799: safe duplicate work
        const int part = tid & 3;
        const int samp = (row2 >= 75);
        const int row  = row2 - 75 * samp;

        const unsigned long long* e1 = ep1[samp];
        const unsigned long long* e2 = ep2[samp];

        const int d  = row % 3;
        const int a3 = row - d;
        const int r0 = d * 25;

        const unsigned long long c0 = e2[a3];
        const unsigned long long c1 = e2[a3 + 1];
        const unsigned long long c2 = e2[a3 + 2];

        const int qs  = (part == 0) ? 0 : part * 6 + 1;   // 0,7,13,19
        const int cnt = (part == 0) ? 7 : 6;

        const int kk0 = (d + qs) % 3;
        unsigned long long ra = (kk0 == 0) ? c0 : ((kk0 == 1) ? c1 : c2);
        unsigned long long rb = (kk0 == 0) ? c1 : ((kk0 == 1) ? c2 : c0);
        unsigned long long rc = (kk0 == 0) ? c2 : ((kk0 == 1) ? c0 : c1);

        float vals[7];
        float sum0 = 0.f, sum1 = 0.f;
        #pragma unroll
        for (int j = 0; j < 7; j++) {
            if (j < cnt) {
                const unsigned long long pr = mul2(e1[r0 + qs + j], ra);
                float pe, pf;
                unpack2(pr, pe, pf);
                const float vl = fmaxf(pe, pf);   // exp2(leaky(e)) by monotonicity
                vals[j] = vl;
                if (j & 1) sum1 += vl; else sum0 += vl;
                unsigned long long t = ra; ra = rb; rb = rc; rc = t;
            }
        }
        float sum = sum0 + sum1;
        sum += __shfl_xor_sync(0xffffffffu, sum, 1);
        sum += __shfl_xor_sync(0xffffffffu, sum, 2);
        const float inv = __fdividef(1.0f, sum);

        if (act) {
            float* og = out + (size_t)(n0 + samp) * 1875 + row * 25 + qs;
            #pragma unroll
            for (int j = 0; j < 7; j++)
                if (j < cnt) og[j] = vals[j] * inv;
        }
    }
}

extern "C" void kernel_launch(void* const* d_in, const int* in_sizes, int n_in,
                              void* d_out, int out_size)
{
    const float* x  = (const float*)d_in[0];
    const float* Wc = (const float*)d_in[1];
    const float* Wa = (const float*)d_in[2];
    float* out = (float*)d_out;
    gat_adj_kernel<<<128, TPB>>>(x, Wc, Wa, out);
}